// round 17
// baseline (speedup 1.0000x reference)
#include <cuda_runtime.h>
#include <cuda_fp16.h>
#include <cstdint>

#define SEQ  512
#define NTHR 512
#define NCTA 128
#define OUTF 72

// ---- SMEM map (bytes) ----
#define OFF_W0  0        // Whh0 fp16 [256 n''][64 k] SW128 (32KB)
#define OFF_W1  32768    // blk0=Wih1, blk1=Whh1 (+32768) (64KB)
#define OFF_A0  98304    // h0 fp16 tile [16 m][64 cell], 2 buffers x 2KB
#define OFF_A1  102400   // h1 fp16 tile, 2 buffers x 2KB
#define OFF_XS  106496   // x chunk [32 s][16 m] f32 (2KB)
#define OFF_H1F 108544   // h1 last, fp32 [16][68]
#define SMEM_BYTES 112896

#define SW128(o) ((o) ^ (((o) >> 3) & 0x70))

__device__ __forceinline__ uint32_t smem_u32(const void* p) {
    uint32_t a;
    asm("{ .reg .u64 t; cvta.to.shared.u64 t, %1; cvt.u32.u64 %0, t; }" : "=r"(a) : "l"(p));
    return a;
}
__device__ __forceinline__ void ldsm4(uint32_t addr, uint32_t r[4]) {
    asm volatile("ldmatrix.sync.aligned.m8n8.x4.shared.b16 {%0,%1,%2,%3}, [%4];"
                 : "=r"(r[0]), "=r"(r[1]), "=r"(r[2]), "=r"(r[3]) : "r"(addr));
}
__device__ __forceinline__ void mma_f16(float d[4], const uint32_t a[4],
                                        uint32_t b0, uint32_t b1) {
    asm("mma.sync.aligned.m16n8k16.row.col.f32.f16.f16.f32 "
        "{%0,%1,%2,%3}, {%4,%5,%6,%7}, {%8,%9}, {%0,%1,%2,%3};"
        : "+f"(d[0]), "+f"(d[1]), "+f"(d[2]), "+f"(d[3])
        : "r"(a[0]), "r"(a[1]), "r"(a[2]), "r"(a[3]), "r"(b0), "r"(b1));
}
__device__ __forceinline__ float tanha(float x) {
    float y; asm("tanh.approx.f32 %0, %1;" : "=f"(y) : "f"(x)); return y;
}
__device__ __forceinline__ __half2 th2(__half2 v) {
    uint32_t u = *reinterpret_cast<uint32_t*>(&v);
    asm("tanh.approx.f16x2 %0, %0;" : "+r"(u));
    return *reinterpret_cast<__half2*>(&u);
}

// Dual-row cell update: gate tanhs packed f16x2 (2 rows/op); c, tanh(c) in f32.
__device__ __forceinline__ void cellup2(float vi0, float vf0, float vg0, float vo0,
                                        float vi1, float vf1, float vg1, float vo1,
                                        float* c, float& h0, float& h1)
{
    __half2 ti = th2(__floats2half2_rn(vi0, vi1));
    __half2 tf = th2(__floats2half2_rn(vf0, vf1));
    __half2 tg = th2(__floats2half2_rn(vg0, vg1));
    __half2 to = th2(__floats2half2_rn(vo0, vo1));
    float i0 = fmaf(__low2float(ti),  0.5f, 0.5f);
    float i1 = fmaf(__high2float(ti), 0.5f, 0.5f);
    float f0 = fmaf(__low2float(tf),  0.5f, 0.5f);
    float f1 = fmaf(__high2float(tf), 0.5f, 0.5f);
    float g0 = __low2float(tg),  g1 = __high2float(tg);
    float o0 = fmaf(__low2float(to),  0.5f, 0.5f);
    float o1 = fmaf(__high2float(to), 0.5f, 0.5f);
    c[0] = fmaf(f0, c[0], i0 * g0);
    c[1] = fmaf(f1, c[1], i1 * g1);
    h0 = o0 * tanha(c[0]);
    h1 = o1 * tanha(c[1]);
}

__global__ __launch_bounds__(NTHR, 1)
void lstm_mma_kernel(const float* __restrict__ x,
                     const float* __restrict__ Wih0, const float* __restrict__ Whh0,
                     const float* __restrict__ bih0, const float* __restrict__ bhh0,
                     const float* __restrict__ Wih1, const float* __restrict__ Whh1,
                     const float* __restrict__ bih1, const float* __restrict__ bhh1,
                     const float* __restrict__ fcw,  const float* __restrict__ fcb,
                     float* __restrict__ out)
{
    extern __shared__ char smem[];
    const uint32_t sb = smem_u32(smem);
    const int tid = threadIdx.x, warp = tid >> 5, lane = tid & 31;
    const int r8 = lane & 7, mid = lane >> 3;

    const uint32_t swz  = (uint32_t)(r8 << 4);
    const uint32_t aRow = (uint32_t)((r8 + ((mid & 1) << 3)) * 128);
    const uint32_t aK2  = (uint32_t)((mid & 2) << 3);
    const uint32_t bRow = (uint32_t)((r8 + ((mid & 2) << 2)) * 128);
    const uint32_t bK2  = (uint32_t)((mid & 1) << 4);

    // ---- weights -> SMEM, fp16, sigmoid rows pre-scaled by 0.5 (exact) ----
    // n'' = w*16 + gp*8 + c*2 + g2 : gate = gp*2+g2, cell = w*4+c  (w = warp 0..15)
    for (int idx = tid; idx < 256 * 64; idx += NTHR) {
        int np = idx >> 6, k = idx & 63;
        int gate = ((np >> 3) & 1) * 2 + (np & 1);
        int cell = (np >> 4) * 4 + ((np >> 1) & 3);
        float sc = (gate == 2) ? 1.0f : 0.5f;
        uint32_t off = SW128((uint32_t)(np * 128 + k * 2));
        *(__half*)(smem + OFF_W0 + off) =
            __float2half_rn(sc * Whh0[(gate * 64 + cell) * 64 + k]);
    }
    for (int idx = tid; idx < 2 * 256 * 64; idx += NTHR) {
        int blk = idx >> 14, rem = idx & 16383;
        int np = rem >> 6, k = rem & 63;
        int gate = ((np >> 3) & 1) * 2 + (np & 1);
        int cell = (np >> 4) * 4 + ((np >> 1) & 3);
        float sc = (gate == 2) ? 1.0f : 0.5f;
        float v = blk ? Whh1[(gate * 64 + cell) * 64 + k] : Wih1[(gate * 64 + cell) * 64 + k];
        uint32_t off = (uint32_t)(blk * 32768) + SW128((uint32_t)(np * 128 + k * 2));
        *(__half*)(smem + OFF_W1 + off) = __float2half_rn(sc * v);
    }
    for (int idx = tid; idx < 8192 / 4; idx += NTHR)
        ((uint32_t*)(smem + OFF_A0))[idx] = 0;

    // ---- per-lane assignment: ONE cell (warp's tile-pair), TWO batch rows ----
    const int m0 = lane >> 2, m1 = m0 + 8;
    const int ct = warp * 4 + (lane & 3);
    float b0a[4], w0a[4], b1a[4];
#pragma unroll
    for (int g = 0; g < 4; ++g) {
        float sc = (g == 2) ? 1.0f : 0.5f;
        b0a[g] = sc * (bih0[g * 64 + ct] + bhh0[g * 64 + ct]);
        w0a[g] = sc * Wih0[g * 64 + ct];
        b1a[g] = sc * (bih1[g * 64 + ct] + bhh1[g * 64 + ct]);
    }
    float c0[2] = {0.f, 0.f}, c1[2] = {0.f, 0.f};
    const uint32_t hoff = (uint32_t)(m0 * 128 + ct * 2) ^ (uint32_t)(m0 << 4);

    float* xs = (float*)(smem + OFF_XS);
    const int gRow = blockIdx.x * 16;

    if (tid < 512) xs[tid] = x[(size_t)(gRow + (tid & 15)) * SEQ + (tid >> 4)];
    __syncthreads();

    // ---- preload weight fragments (warp owns 16 n''-cols at base warp*2048) ----
    uint32_t f0[4][4], f1a[4][4], f1b[4][4];
#pragma unroll
    for (int kc = 0; kc < 4; ++kc) {
        uint32_t colB = ((uint32_t)(kc * 32) + bK2) ^ swz;
        uint32_t base = (uint32_t)(warp * 2048) + bRow + colB;
        ldsm4(sb + OFF_W0 + base, f0[kc]);
        ldsm4(sb + OFF_W1 + base, f1a[kc]);
        ldsm4(sb + OFF_W1 + 32768 + base, f1b[kc]);
    }

    // ---- prologue: h0(0) = f(x(0)) -> A0 buf0 ----
    {
        const float xi0 = xs[m0], xi1 = xs[m1];
        float h0v, h1v;
        cellup2(w0a[0]*xi0 + b0a[0], w0a[1]*xi0 + b0a[1],
                w0a[2]*xi0 + b0a[2], w0a[3]*xi0 + b0a[3],
                w0a[0]*xi1 + b0a[0], w0a[1]*xi1 + b0a[1],
                w0a[2]*xi1 + b0a[2], w0a[3]*xi1 + b0a[3], c0, h0v, h1v);
        *(__half*)(smem + OFF_A0 + hoff)        = __float2half_rn(h0v);
        *(__half*)(smem + OFF_A0 + hoff + 1024) = __float2half_rn(h1v);
    }
    __syncthreads();

    const bool oddw = warp & 1;

    // ================= main loop: ONE barrier per step, staggered phases ========
    for (int s = 0; s < SEQ; ++s) {
        if (((s + 1) & 31) == 0 && (s + 1) < SEQ) {
            if (tid < 512)
                xs[tid] = x[(size_t)(gRow + (tid & 15)) * SEQ + (s + 1) + (tid >> 4)];
            __syncthreads();
        }
        const int rb = s & 1;
        const uint32_t A0r = sb + OFF_A0 + (uint32_t)(rb * 2048);
        const uint32_t A1r = sb + OFF_A1 + (uint32_t)(rb * 2048);
        const uint32_t A0w = sb + OFF_A0 + (uint32_t)((1 - rb) * 2048);
        const uint32_t A1w = sb + OFF_A1 + (uint32_t)((1 - rb) * 2048);

        float d0[2][4], d1[2][4];
#pragma unroll
        for (int u = 0; u < 2; ++u) {
            d0[u][0] = d0[u][1] = d0[u][2] = d0[u][3] = 0.f;
            d1[u][0] = d1[u][1] = d1[u][2] = d1[u][3] = 0.f;
        }

        uint32_t af[4][4];

        if (oddw) {
            // ---- ODD warps: d1b FIRST (bf-ldsm + tensor), then af path ----
#pragma unroll
            for (int kc = 0; kc < 4; ++kc) {
                uint32_t bf[4];
                ldsm4(A1r + aRow + ((((uint32_t)(kc * 32)) + aK2) ^ swz), bf);
                mma_f16(d1[0], bf, f1b[kc][0], f1b[kc][1]);
                mma_f16(d1[1], bf, f1b[kc][2], f1b[kc][3]);
            }
#pragma unroll
            for (int kc = 0; kc < 4; ++kc)
                ldsm4(A0r + aRow + ((((uint32_t)(kc * 32)) + aK2) ^ swz), af[kc]);
#pragma unroll
            for (int kc = 0; kc < 4; ++kc) {
                mma_f16(d0[0], af[kc], f0[kc][0], f0[kc][1]);
                mma_f16(d0[1], af[kc], f0[kc][2], f0[kc][3]);
            }
#pragma unroll
            for (int kc = 0; kc < 4; ++kc) {
                mma_f16(d1[0], af[kc], f1a[kc][0], f1a[kc][1]);
                mma_f16(d1[1], af[kc], f1a[kc][2], f1a[kc][3]);
            }
        } else {
            // ---- EVEN warps: af path FIRST, bf/d1b deferred to after epi-L0 ----
#pragma unroll
            for (int kc = 0; kc < 4; ++kc)
                ldsm4(A0r + aRow + ((((uint32_t)(kc * 32)) + aK2) ^ swz), af[kc]);
#pragma unroll
            for (int kc = 0; kc < 4; ++kc) {
                mma_f16(d0[0], af[kc], f0[kc][0], f0[kc][1]);
                mma_f16(d0[1], af[kc], f0[kc][2], f0[kc][3]);
            }
#pragma unroll
            for (int kc = 0; kc < 4; ++kc) {
                mma_f16(d1[0], af[kc], f1a[kc][0], f1a[kc][1]);
                mma_f16(d1[1], af[kc], f1a[kc][2], f1a[kc][3]);
            }
        }

        // ---- epi L0(s+1) ----
        {
            const int sn = (s + 1 < SEQ) ? (s + 1) : s;
            const float xi0 = xs[(sn & 31) * 16 + m0];
            const float xi1 = xs[(sn & 31) * 16 + m1];
            float h0v, h1v;
            cellup2(d0[0][0] + b0a[0] + w0a[0]*xi0, d0[0][1] + b0a[1] + w0a[1]*xi0,
                    d0[1][0] + b0a[2] + w0a[2]*xi0, d0[1][1] + b0a[3] + w0a[3]*xi0,
                    d0[0][2] + b0a[0] + w0a[0]*xi1, d0[0][3] + b0a[1] + w0a[1]*xi1,
                    d0[1][2] + b0a[2] + w0a[2]*xi1, d0[1][3] + b0a[3] + w0a[3]*xi1,
                    c0, h0v, h1v);
            *(__half*)(smem + (A0w - sb) + hoff)        = __float2half_rn(h0v);
            *(__half*)(smem + (A0w - sb) + hoff + 1024) = __float2half_rn(h1v);
        }

        if (!oddw) {
            // ---- EVEN warps: d1b now (overlaps odd warps' epi) ----
#pragma unroll
            for (int kc = 0; kc < 4; ++kc) {
                uint32_t bf[4];
                ldsm4(A1r + aRow + ((((uint32_t)(kc * 32)) + aK2) ^ swz), bf);
                mma_f16(d1[0], bf, f1b[kc][0], f1b[kc][1]);
                mma_f16(d1[1], bf, f1b[kc][2], f1b[kc][3]);
            }
        }

        // ---- epi L1(s) ----
        {
            float h0v, h1v;
            cellup2(d1[0][0] + b1a[0], d1[0][1] + b1a[1],
                    d1[1][0] + b1a[2], d1[1][1] + b1a[3],
                    d1[0][2] + b1a[0], d1[0][3] + b1a[1],
                    d1[1][2] + b1a[2], d1[1][3] + b1a[3], c1, h0v, h1v);
            *(__half*)(smem + (A1w - sb) + hoff)        = __float2half_rn(h0v);
            *(__half*)(smem + (A1w - sb) + hoff + 1024) = __float2half_rn(h1v);
            if (s == SEQ - 1) {
                ((float*)(smem + OFF_H1F))[m0 * 68 + ct] = h0v;
                ((float*)(smem + OFF_H1F))[m1 * 68 + ct] = h1v;
            }
        }
        __syncthreads();
    }

    // ================= final FC: out = h1(S-1) @ fcw^T + fcb =================
    const float* h1f = (const float*)(smem + OFF_H1F);
    for (int idx = tid; idx < 16 * OUTF; idx += NTHR) {
        int r = idx / OUTF, o = idx - r * OUTF;
        float acc = fcb[o];
#pragma unroll 16
        for (int k = 0; k < 64; ++k)
            acc = fmaf(h1f[r * 68 + k], fcw[o * 64 + k], acc);
        out[(gRow + r) * OUTF + o] = acc;
    }
}

extern "C" void kernel_launch(void* const* d_in, const int* in_sizes, int n_in,
                              void* d_out, int out_size)
{
    (void)in_sizes; (void)n_in; (void)out_size;
    cudaFuncSetAttribute(lstm_mma_kernel,
                         cudaFuncAttributeMaxDynamicSharedMemorySize, SMEM_BYTES);
    lstm_mma_kernel<<<NCTA, NTHR, SMEM_BYTES>>>(
        (const float*)d_in[0],  (const float*)d_in[1],  (const float*)d_in[2],
        (const float*)d_in[3],  (const float*)d_in[4],  (const float*)d_in[5],
        (const float*)d_in[6],  (const float*)d_in[7],  (const float*)d_in[8],
        (const float*)d_in[9],  (const float*)d_in[10], (float*)d_out);
}